// round 15
// baseline (speedup 1.0000x reference)
#include <cuda_runtime.h>
#include <cuda_fp16.h>
#include <math.h>
#include <stdint.h>

// ---------------- problem constants ----------------
#define BATCH   128
#define CHAN    3
#define HW      224
#define PATCH   16
#define NPD     14
#define NPATCH  (NPD*NPD)           // 196
#define M_DIM   (BATCH*NPATCH)      // 25088
#define K_DIM   (CHAN*PATCH*PATCH)  // 768
#define N_DIM   768
#define IMG_STRIDE (CHAN*HW*HW)     // 150528
#define CH_STRIDE  (HW*HW)          // 50176

#define PI_D 3.141592653589793238462643383279502884

// fp16 scratch: DCT-folded weights [n][k]
__device__ __half g_wt[N_DIM * K_DIM];

// f32-accumulate fp16 MMA
__device__ __forceinline__ void mma_f16(float* c, const unsigned* a, const unsigned* b) {
    asm volatile(
        "mma.sync.aligned.m16n8k16.row.col.f32.f16.f16.f32 "
        "{%0,%1,%2,%3}, {%4,%5,%6,%7}, {%8,%9}, {%0,%1,%2,%3};"
        : "+f"(c[0]), "+f"(c[1]), "+f"(c[2]), "+f"(c[3])
        : "r"(a[0]), "r"(a[1]), "r"(a[2]), "r"(a[3]), "r"(b[0]), "r"(b[1]));
}
#define LDSM_X4(r0, r1, r2, r3, addr) \
    asm volatile("ldmatrix.sync.aligned.m8n8.x4.shared.b16 {%0,%1,%2,%3}, [%4];" \
                 : "=r"(r0), "=r"(r1), "=r"(r2), "=r"(r3) : "r"(addr))
#define CP_ASYNC16(saddr, gptr) \
    asm volatile("cp.async.cg.shared.global [%0], [%1], 16;" :: "r"(saddr), "l"(gptr))
#define CP_COMMIT()  asm volatile("cp.async.commit_group;" ::: "memory")
#define CP_WAIT(n)   asm volatile("cp.async.wait_group %0;" :: "n"(n) : "memory")

// ---------------------------------------------------------------------------
// Kernel 1: fold per-8x8 DCT into conv weights (w' = D^T W D), fp16, [n][k].
// ---------------------------------------------------------------------------
__global__ void dct_weight_kernel(const float* __restrict__ w) {
    __shared__ float Ws[16][16];
    __shared__ float Ds[8][8];
    int o = blockIdx.x / CHAN, c = blockIdx.x % CHAN, tid = threadIdx.x;
    if (tid < 64) {
        int k = tid >> 3, n = tid & 7;
        double v = sqrt(2.0 / 8.0) * cos(PI_D * (2.0 * n + 1.0) * k / 16.0);
        if (k == 0) v *= (1.0 / sqrt(2.0));
        Ds[k][n] = (float)v;
    }
    Ws[tid >> 4][tid & 15] = w[(o * CHAN + c) * 256 + tid];
    __syncthreads();
    int i = tid >> 4, j = tid & 15;
    int bi = i & 8, bj = j & 8, ii = i & 7, jj = j & 7;
    float s = 0.0f;
    #pragma unroll
    for (int u = 0; u < 8; u++) {
        float du = Ds[u][ii];
        #pragma unroll
        for (int v = 0; v < 8; v++) s += du * Ws[bi + u][bj + v] * Ds[v][jj];
    }
    g_wt[(long)o * K_DIM + c * 256 + i * 16 + j] = __float2half_rn(s);
}

// ---------------------------------------------------------------------------
// Kernel 2: fp16 mma.sync m16n8k16 GEMM with FUSED im2col+convert on A.
//   A: cp.async fp32 directly from x (patch addressing), fragments built with
//      LDS.64 + cvt-to-half2 (hides under the mma-rate-bound loop).
//   B: fp16 [n][k] from dct kernel, ldmatrix fragments (ROWB=80 conflict-free).
//   BM=128 BN=128 BK=32, 3-stage cp.async, 2 CTAs/SM, 8 warps (4m x 2n),
//   f32 accumulators.
// ---------------------------------------------------------------------------
#define BM 128
#define BN 128
#define BK 32
#define STAGES 3
#define NT (K_DIM / BK)          // 24
#define ROWF 40                  // A row stride in floats (32 data + 8 pad)
#define A_BYTES (BM * ROWF * 4)  // 20480
#define ROWB 80                  // B row stride in bytes (64 data + 16 pad)
#define B_BYTES (BM * ROWB)      // 10240
#define STG_B (A_BYTES + B_BYTES)     // 30720
#define SMEM_BYTES (STAGES * STG_B)   // 92160

__global__ __launch_bounds__(256, 2)
void gemm_fused_kernel(const float* __restrict__ x,
                       const float* __restrict__ bias,
                       float* __restrict__ out) {
    extern __shared__ char smem[];
    const unsigned smem_b = (unsigned)__cvta_generic_to_shared(smem);
    const int tid  = threadIdx.x;
    const int lane = tid & 31, wid = tid >> 5;
    const int warp_m = wid >> 1, warp_n = wid & 1;
    const int g = lane >> 2, tig = lane & 3;

    const int m0 = blockIdx.y * BM;
    const int n0 = blockIdx.x * BN;

    // ---- A global-load mapping (fp32 from x): 1024 16B chunks, 4/thread ----
    const int arow = tid >> 3;     // 0..31 ; rows arow + 32*s
    const int qa   = tid & 7;      // 16B chunk within the 32-float k row
    const int kq4  = qa >> 2;      // second patch-row (k 16..31)
    const int jof  = (qa & 3) * 4; // column offset inside patch row
    long abase[4];
    #pragma unroll
    for (int s = 0; s < 4; s++) {
        int m = m0 + arow + 32 * s;
        int b = m / NPATCH, pr = m % NPATCH;
        abase[s] = (long)b * IMG_STRIDE + (long)(pr / NPD) * (PATCH * HW)
                 + (long)(pr % NPD) * PATCH;
    }
    const unsigned stA = arow * ROWF * 4 + qa * 16;   // smem byte offset (row, chunk)

    // ---- B global-load mapping (fp16): 512 16B chunks, 2/thread ----
    const int brow = tid >> 2;     // rows brow, brow+64
    const int qb   = tid & 3;
    const __half* gB0 = g_wt + (long)(n0 + brow) * K_DIM + qb * 8;
    const __half* gB1 = g_wt + (long)(n0 + brow + 64) * K_DIM + qb * 8;
    const unsigned stB0 = brow * ROWB + qb * 16;
    const unsigned stB1 = (brow + 64) * ROWB + qb * 16;

    auto load_tile = [&](int t, int slot) {
        const unsigned base = smem_b + slot * STG_B;
        const int k0 = t * BK;
        const int c  = k0 >> 8;
        const int i0 = (k0 & 255) >> 4;
        const long aoff = (long)c * CH_STRIDE + (long)(i0 + kq4) * HW + jof;
        #pragma unroll
        for (int s = 0; s < 4; s++)
            CP_ASYNC16(base + stA + s * (32 * ROWF * 4), x + abase[s] + aoff);
        CP_ASYNC16(base + A_BYTES + stB0, gB0 + k0);
        CP_ASYNC16(base + A_BYTES + stB1, gB1 + k0);
    };

    // ---- B ldmatrix per-thread offsets (within a stage) ----
    const int lm_row = lane & 7;
    const int b_hi = (lane >> 3) & 1;      // +8 k cols for mats 1,3
    const int b_nt = (lane >> 4);          // second n-tile for mats 2,3
    unsigned b_off[4];
    #pragma unroll
    for (int g2 = 0; g2 < 4; g2++)
        b_off[g2] = A_BYTES + (warp_n * 64 + (2 * g2 + b_nt) * 8 + lm_row) * ROWB
                  + b_hi * 16;

    // ---- A fragment float2 offsets (bytes): rows warp_m*32+mt*16+{g,g+8} ----
    // a0: (row g,    k 2tig..), a1: (row g+8), a2: (row g, k+8), a3: (row g+8, k+8)
    unsigned a_ld[2][2];   // [mt][rowhalf] -> byte offset of float2 at k-base
    #pragma unroll
    for (int mt = 0; mt < 2; mt++) {
        a_ld[mt][0] = (warp_m * 32 + mt * 16 + g) * ROWF * 4 + tig * 8;
        a_ld[mt][1] = (warp_m * 32 + mt * 16 + 8 + g) * ROWF * 4 + tig * 8;
    }

    float acc[2][8][4];
    #pragma unroll
    for (int i = 0; i < 2; i++)
        #pragma unroll
        for (int j = 0; j < 8; j++)
            #pragma unroll
            for (int p = 0; p < 4; p++) acc[i][j][p] = 0.0f;

    #pragma unroll
    for (int s = 0; s < STAGES - 1; s++) { load_tile(s, s); CP_COMMIT(); }

    auto compute_tile = [&](unsigned base) {
        const char* As = smem + (base - smem_b);   // generic pointer for LDS
        #pragma unroll
        for (int kk = 0; kk < 2; kk++) {          // two k16 steps per BK=32
            unsigned afr[2][4];
            #pragma unroll
            for (int mt = 0; mt < 2; mt++) {
                float2 p0 = *(const float2*)(As + a_ld[mt][0] + kk * 64);
                float2 p1 = *(const float2*)(As + a_ld[mt][1] + kk * 64);
                float2 p2 = *(const float2*)(As + a_ld[mt][0] + kk * 64 + 32);
                float2 p3 = *(const float2*)(As + a_ld[mt][1] + kk * 64 + 32);
                __half2 h0 = __floats2half2_rn(p0.x, p0.y);
                __half2 h1 = __floats2half2_rn(p1.x, p1.y);
                __half2 h2 = __floats2half2_rn(p2.x, p2.y);
                __half2 h3 = __floats2half2_rn(p3.x, p3.y);
                afr[mt][0] = *(unsigned*)&h0;
                afr[mt][1] = *(unsigned*)&h1;
                afr[mt][2] = *(unsigned*)&h2;
                afr[mt][3] = *(unsigned*)&h3;
            }
            unsigned bfr[8][2];
            #pragma unroll
            for (int g2 = 0; g2 < 4; g2++)
                LDSM_X4(bfr[2 * g2][0], bfr[2 * g2][1],
                        bfr[2 * g2 + 1][0], bfr[2 * g2 + 1][1],
                        base + b_off[g2] + kk * 32);
            #pragma unroll
            for (int mt = 0; mt < 2; mt++)
                #pragma unroll
                for (int nt = 0; nt < 8; nt++)
                    mma_f16(acc[mt][nt], afr[mt], bfr[nt]);
        }
    };

    // main loop: NT=24, unrolled by 3 so slot indices are compile-time.
    for (int t0 = 0; t0 < NT; t0 += STAGES) {
        #pragma unroll
        for (int u = 0; u < STAGES; u++) {
            const int t = t0 + u;
            CP_WAIT(STAGES - 2);
            __syncthreads();
            const int tn = t + STAGES - 1;
            if (tn < NT) load_tile(tn, (u + STAGES - 1) % STAGES);
            CP_COMMIT();
            compute_tile(smem_b + u * STG_B);
        }
    }

    // ---- epilogue: bias + store ----
    #pragma unroll
    for (int mt = 0; mt < 2; mt++) {
        const int r0 = m0 + warp_m * 32 + mt * 16 + g;
        #pragma unroll
        for (int nt = 0; nt < 8; nt++) {
            const int col = n0 + warp_n * 64 + nt * 8 + 2 * tig;
            const float b0 = bias[col], b1 = bias[col + 1];
            float2 v0 = make_float2(acc[mt][nt][0] + b0, acc[mt][nt][1] + b1);
            float2 v1 = make_float2(acc[mt][nt][2] + b0, acc[mt][nt][3] + b1);
            *(float2*)(out + (long)r0 * N_DIM + col)       = v0;
            *(float2*)(out + (long)(r0 + 8) * N_DIM + col) = v1;
        }
    }
}

// ---------------------------------------------------------------------------
extern "C" void kernel_launch(void* const* d_in, const int* in_sizes, int n_in,
                              void* d_out, int out_size) {
    const float* x = (const float*)d_in[0];   // [128,3,224,224]
    const float* w = (const float*)d_in[1];   // [768,3,16,16]
    const float* b = (const float*)d_in[2];   // [768]
    float* out = (float*)d_out;               // [128,196,768]

    cudaFuncSetAttribute(gemm_fused_kernel,
                         cudaFuncAttributeMaxDynamicSharedMemorySize, SMEM_BYTES);

    dct_weight_kernel<<<N_DIM * CHAN, 256>>>(w);
    gemm_fused_kernel<<<dim3(N_DIM / BN, M_DIM / BM), 256, SMEM_BYTES>>>(x, b, out);
}

// round 16
// speedup vs baseline: 1.0882x; 1.0882x over previous
#include <cuda_runtime.h>
#include <cuda_fp16.h>
#include <math.h>
#include <stdint.h>

// ---------------- problem constants ----------------
#define BATCH   128
#define CHAN    3
#define HW      224
#define PATCH   16
#define NPD     14
#define NPATCH  (NPD*NPD)           // 196
#define M_DIM   (BATCH*NPATCH)      // 25088
#define K_DIM   (CHAN*PATCH*PATCH)  // 768
#define N_DIM   768

#define PI_D 3.141592653589793238462643383279502884

// fp16 scratch: DCT-folded weights [n][k]; im2col'd input [m][k]
__device__ __half g_wt[N_DIM * K_DIM];
__device__ __half g_xh[(long)M_DIM * K_DIM];

__device__ __forceinline__ void mma_f16(float* c, const unsigned* a, const unsigned* b) {
    asm volatile(
        "mma.sync.aligned.m16n8k16.row.col.f32.f16.f16.f32 "
        "{%0,%1,%2,%3}, {%4,%5,%6,%7}, {%8,%9}, {%0,%1,%2,%3};"
        : "+f"(c[0]), "+f"(c[1]), "+f"(c[2]), "+f"(c[3])
        : "r"(a[0]), "r"(a[1]), "r"(a[2]), "r"(a[3]), "r"(b[0]), "r"(b[1]));
}
#define LDSM_X4(r0, r1, r2, r3, addr) \
    asm volatile("ldmatrix.sync.aligned.m8n8.x4.shared.b16 {%0,%1,%2,%3}, [%4];" \
                 : "=r"(r0), "=r"(r1), "=r"(r2), "=r"(r3) : "r"(addr))
#define CP_ASYNC16(saddr, gptr) \
    asm volatile("cp.async.cg.shared.global [%0], [%1], 16;" :: "r"(saddr), "l"(gptr))
#define CP_COMMIT()  asm volatile("cp.async.commit_group;" ::: "memory")
#define CP_WAIT(n)   asm volatile("cp.async.wait_group %0;" :: "n"(n) : "memory")

// ---------------------------------------------------------------------------
// Kernel 0 (combined prep): blocks [0, NB_IM2COL) do im2col (16 floats each
// thread); blocks [NB_IM2COL, NB_IM2COL+NB_DCT) fold the DCT into the weights.
// ---------------------------------------------------------------------------
#define NF16       (BATCH * CHAN * HW * HW / 16)   // 1,204,224 16-float chunks
#define NB_IM2COL  (NF16 / 256)                    // 4704
#define NB_DCT     (N_DIM * CHAN)                  // 2304

__global__ void prep_kernel(const float* __restrict__ x, const float* __restrict__ w) {
    if (blockIdx.x < NB_IM2COL) {
        // ---- im2col: x (fp32 NCHW) -> g_xh (fp16 [m][k]) ----
        int f = blockIdx.x * blockDim.x + threadIdx.x;   // 16-float chunk
        const float4* xp = (const float4*)x + (long)f * 4;
        float4 v0 = xp[0], v1 = xp[1], v2 = xp[2], v3 = xp[3];
        int w16 = f % 14; int rest = f / 14;             // 14 chunks per row
        int h = rest % HW; rest /= HW;
        int c = rest % CHAN; int b = rest / CHAN;
        int pw = w16;                                    // chunk == one patch row
        int i = h & 15, ph = h >> 4;
        long m = (long)b * NPATCH + ph * NPD + pw;
        int  k = c * 256 + i * 16;
        __half2 h0 = __floats2half2_rn(v0.x, v0.y);
        __half2 h1 = __floats2half2_rn(v0.z, v0.w);
        __half2 h2 = __floats2half2_rn(v1.x, v1.y);
        __half2 h3 = __floats2half2_rn(v1.z, v1.w);
        __half2 h4 = __floats2half2_rn(v2.x, v2.y);
        __half2 h5 = __floats2half2_rn(v2.z, v2.w);
        __half2 h6 = __floats2half2_rn(v3.x, v3.y);
        __half2 h7 = __floats2half2_rn(v3.z, v3.w);
        uint4 o0, o1;
        o0.x = *(unsigned*)&h0; o0.y = *(unsigned*)&h1;
        o0.z = *(unsigned*)&h2; o0.w = *(unsigned*)&h3;
        o1.x = *(unsigned*)&h4; o1.y = *(unsigned*)&h5;
        o1.z = *(unsigned*)&h6; o1.w = *(unsigned*)&h7;
        uint4* dst = (uint4*)(g_xh + m * K_DIM + k);
        dst[0] = o0; dst[1] = o1;
    } else {
        // ---- DCT weight fold: w' = D^T W D per 8x8 sub-block, fp16 [n][k] ----
        __shared__ float Ws[16][16];
        __shared__ float Ds[8][8];
        int blk = blockIdx.x - NB_IM2COL;
        int o = blk / CHAN, c = blk % CHAN, tid = threadIdx.x;
        if (tid < 64) {
            int k = tid >> 3, n = tid & 7;
            double v = sqrt(2.0 / 8.0) * cos(PI_D * (2.0 * n + 1.0) * k / 16.0);
            if (k == 0) v *= (1.0 / sqrt(2.0));
            Ds[k][n] = (float)v;
        }
        Ws[tid >> 4][tid & 15] = w[(o * CHAN + c) * 256 + tid];
        __syncthreads();
        int i = tid >> 4, j = tid & 15;
        int bi = i & 8, bj = j & 8, ii = i & 7, jj = j & 7;
        float s = 0.0f;
        #pragma unroll
        for (int u = 0; u < 8; u++) {
            float du = Ds[u][ii];
            #pragma unroll
            for (int v = 0; v < 8; v++) s += du * Ws[bi + u][bj + v] * Ds[v][jj];
        }
        g_wt[(long)o * K_DIM + c * 256 + i * 16 + j] = __float2half_rn(s);
    }
}

// ---------------------------------------------------------------------------
// Kernel 1: fp16 mma.sync m16n8k16 GEMM with ldmatrix fragment loads.
//   (proven R10 configuration: best measured GEMM)
//   BM=128 BN=128 BK=32, 4-stage cp.async, 2 CTAs/SM, 8 warps (4m x 2n),
//   warp tile 32x64, f32 accumulators.  K-major fp16 smem, 80B row stride.
// ---------------------------------------------------------------------------
#define BM 128
#define BN 128
#define BK 32
#define STAGES 4
#define NT (K_DIM / BK)          // 24
#define ROWB 80                  // bytes per smem row (64 data + 16 pad)
#define TILE_B (BM * ROWB)       // 10240 bytes per operand tile
#define STG_B (2 * TILE_B)       // A then B : 20480
#define SMEM_BYTES (STAGES * STG_B)   // 81920

__global__ __launch_bounds__(256, 2)
void gemm_f16_kernel(const float* __restrict__ bias, float* __restrict__ out) {
    extern __shared__ __half smem[];
    const unsigned smem_b = (unsigned)__cvta_generic_to_shared(smem);
    const int tid  = threadIdx.x;
    const int lane = tid & 31, wid = tid >> 5;
    const int warp_m = wid >> 1, warp_n = wid & 1;
    const int g = lane >> 2, tig = lane & 3;

    const int m0 = blockIdx.y * BM;
    const int n0 = blockIdx.x * BN;

    const int row0 = tid >> 2;      // rows row0, row0+64
    const int q    = tid & 3;       // 16B chunk within 64B k-row

    const __half* gA0 = g_xh + (long)(m0 + row0) * K_DIM + q * 8;
    const __half* gA1 = g_xh + (long)(m0 + row0 + 64) * K_DIM + q * 8;
    const __half* gB0 = g_wt + (long)(n0 + row0) * K_DIM + q * 8;
    const __half* gB1 = g_wt + (long)(n0 + row0 + 64) * K_DIM + q * 8;

    const unsigned stA0 = row0 * ROWB + q * 16;
    const unsigned stA1 = (row0 + 64) * ROWB + q * 16;

    auto load_tile = [&](int t, int slot) {
        const unsigned base = smem_b + slot * STG_B;
        const int k0 = t * BK;
        CP_ASYNC16(base + stA0, gA0 + k0);
        CP_ASYNC16(base + stA1, gA1 + k0);
        CP_ASYNC16(base + TILE_B + stA0, gB0 + k0);
        CP_ASYNC16(base + TILE_B + stA1, gB1 + k0);
    };

    const int lm_row = lane & 7;
    const int lm_hi  = (lane >> 3) & 1;
    const int lm_k8  = (lane >> 4) * 8;
    unsigned a_off[2];
    #pragma unroll
    for (int mt = 0; mt < 2; mt++)
        a_off[mt] = (warp_m * 32 + mt * 16 + lm_hi * 8 + lm_row) * ROWB + lm_k8 * 2;
    const int b_hi = (lane >> 3) & 1;
    const int b_nt = (lane >> 4);
    unsigned b_off[4];
    #pragma unroll
    for (int g2 = 0; g2 < 4; g2++)
        b_off[g2] = TILE_B + (warp_n * 64 + (2 * g2 + b_nt) * 8 + lm_row) * ROWB
                  + b_hi * 16;

    float acc[2][8][4];
    #pragma unroll
    for (int i = 0; i < 2; i++)
        #pragma unroll
        for (int j = 0; j < 8; j++)
            #pragma unroll
            for (int p = 0; p < 4; p++) acc[i][j][p] = 0.0f;

    #pragma unroll
    for (int s = 0; s < STAGES - 1; s++) { load_tile(s, s); CP_COMMIT(); }

    auto compute_tile = [&](unsigned base) {
        #pragma unroll
        for (int kk = 0; kk < 2; kk++) {
            unsigned afr[2][4];
            #pragma unroll
            for (int mt = 0; mt < 2; mt++)
                LDSM_X4(afr[mt][0], afr[mt][1], afr[mt][2], afr[mt][3],
                        base + a_off[mt] + kk * 32);
            unsigned bfr[8][2];
            #pragma unroll
            for (int g2 = 0; g2 < 4; g2++)
                LDSM_X4(bfr[2 * g2][0], bfr[2 * g2][1],
                        bfr[2 * g2 + 1][0], bfr[2 * g2 + 1][1],
                        base + b_off[g2] + kk * 32);
            #pragma unroll
            for (int mt = 0; mt < 2; mt++)
                #pragma unroll
                for (int nt = 0; nt < 8; nt++)
                    mma_f16(acc[mt][nt], afr[mt], bfr[nt]);
        }
    };

    for (int t0 = 0; t0 < NT; t0 += STAGES) {
        #pragma unroll
        for (int u = 0; u < STAGES; u++) {
            const int t = t0 + u;
            CP_WAIT(STAGES - 2);
            __syncthreads();
            const int tn = t + STAGES - 1;
            if (tn < NT) load_tile(tn, tn & (STAGES - 1));
            CP_COMMIT();
            compute_tile(smem_b + u * STG_B);
        }
    }

    // ---- epilogue: bias + store ----
    #pragma unroll
    for (int mt = 0; mt < 2; mt++) {
        const int r0 = m0 + warp_m * 32 + mt * 16 + g;
        #pragma unroll
        for (int nt = 0; nt < 8; nt++) {
            const int col = n0 + warp_n * 64 + nt * 8 + 2 * tig;
            const float b0 = bias[col], b1 = bias[col + 1];
            float2 v0 = make_float2(acc[mt][nt][0] + b0, acc[mt][nt][1] + b1);
            float2 v1 = make_float2(acc[mt][nt][2] + b0, acc[mt][nt][3] + b1);
            *(float2*)(out + (long)r0 * N_DIM + col)       = v0;
            *(float2*)(out + (long)(r0 + 8) * N_DIM + col) = v1;
        }
    }
}

// ---------------------------------------------------------------------------
extern "C" void kernel_launch(void* const* d_in, const int* in_sizes, int n_in,
                              void* d_out, int out_size) {
    const float* x = (const float*)d_in[0];   // [128,3,224,224]
    const float* w = (const float*)d_in[1];   // [768,3,16,16]
    const float* b = (const float*)d_in[2];   // [768]
    float* out = (float*)d_out;               // [128,196,768]

    cudaFuncSetAttribute(gemm_f16_kernel,
                         cudaFuncAttributeMaxDynamicSharedMemorySize, SMEM_BYTES);

    prep_kernel<<<NB_IM2COL + NB_DCT, 256>>>(x, w);
    gemm_f16_kernel<<<dim3(N_DIM / BN, M_DIM / BM), 256, SMEM_BYTES>>>(b, out);
}